// round 13
// baseline (speedup 1.0000x reference)
#include <cuda_runtime.h>

// Problem constants
#define TT    4096
#define EMB   1024
#define H2    512
#define G4    2048       // 4 * H2
#define NTAGS 5
#define START 3
#define STOP  4
#define NEGV  -10000.0f

// Recurrence: 64 CTAs per direction, 8 hidden units each (R12 structure)
#define NCTA   64
#define HPER   8
#define NREP   8         // sync replication factor
#define SWIN   8         // sync ring depth (slot = t & 7)
#define CHUNK  128       // GEMM t-tile = gating granularity
#define NCHUNK (TT / CHUNK)   // 32
#define NBLK   16        // gate-col 128-tiles per chunk per dir

typedef unsigned long long u64;

// -------------------- scratch (static device globals; no allocs) ------------
__device__ float d_G[2][TT * G4];               // input preactivations (64 MB)
__device__ float d_h[2][TT * H2];               // hidden history for feats (16 MB)
__device__ unsigned d_sync[2][NREP][SWIN][H2 * 2];  // (h,tag) pairs — 512 KB, L2-hot
__device__ float d_feats[TT * 8];               // tag scores, stride 8
__device__ int   d_cnt[2][NCHUNK];              // per-(dir,chunk) GEMM completion

// -------------------- helpers ----------------------------------------------
__device__ __forceinline__ uint4 ld_rlx_v4u(const unsigned* p) {
    uint4 v;
    asm volatile("ld.relaxed.gpu.global.v4.u32 {%0,%1,%2,%3}, [%4];"
                 : "=r"(v.x), "=r"(v.y), "=r"(v.z), "=r"(v.w) : "l"(p) : "memory");
    return v;
}
__device__ __forceinline__ void st_rlx_pair(unsigned* p, unsigned hbits, unsigned tag) {
    unsigned long long v = ((unsigned long long)tag << 32) | (unsigned long long)hbits;
    asm volatile("st.relaxed.gpu.global.b64 [%0], %1;" :: "l"(p), "l"(v) : "memory");
}
__device__ __forceinline__ int ld_acq_s32(const int* p) {
    int v;
    asm volatile("ld.acquire.gpu.global.b32 %0, [%1];" : "=r"(v) : "l"(p) : "memory");
    return v;
}
__device__ __forceinline__ void red_rel_add(int* p) {
    asm volatile("red.release.gpu.global.add.u32 [%0], 1;" :: "l"(p) : "memory");
}
__device__ __forceinline__ float tanh_fast(float x) {
    float y;
    asm("tanh.approx.f32 %0, %1;" : "=f"(y) : "f"(x));
    return y;
}
__device__ __forceinline__ float sigmoid_fast(float x) {
    return fmaf(0.5f, tanh_fast(0.5f * x), 0.5f);
}
__device__ __forceinline__ u64 fma2(u64 a, u64 b, u64 c) {
    u64 d;
    asm("fma.rn.f32x2 %0, %1, %2, %3;" : "=l"(d) : "l"(a), "l"(b), "l"(c));
    return d;
}
__device__ __forceinline__ void unpack2(u64 v, float& lo, float& hi) {
    asm("mov.b64 {%0, %1}, %2;" : "=f"(lo), "=f"(hi) : "l"(v));
}

// -------------------- kernel: init sync ring tags + counters -----------------
// d_sync = 2*8*8*1024 uints = 131072 uints = 32768 uint4
__global__ void k_init() {
    int i = blockIdx.x * blockDim.x + threadIdx.x;
    uint4 s; s.x = 0xFFFFFFFFu; s.y = 0xFFFFFFFFu; s.z = 0xFFFFFFFFu; s.w = 0xFFFFFFFFu;
    if (i < 32768) ((uint4*)d_sync)[i] = s;
    if (i < 2 * NCHUNK) ((int*)d_cnt)[i] = 0;
}

// -------------------- fused kernel: recurrence + streaming input GEMM --------
// bids 0..127:    persistent LSTM recurrence (R12 code + chunk gating)
// bids 128..1151: GEMM tiles G = embed[sent] @ Wih^T + bias, chunk-major order,
//                 releasing d_cnt[dir][chunk] (16 arrivals per chunk per dir).
__global__ void __launch_bounds__(256) k_main(
    const int*   __restrict__ sent,  const float* __restrict__ embed,
    const float* __restrict__ Wih_f, const float* __restrict__ Whh_f,
    const float* __restrict__ bih_f, const float* __restrict__ bhh_f,
    const float* __restrict__ Wih_b, const float* __restrict__ Whh_b,
    const float* __restrict__ bih_b, const float* __restrict__ bhh_b,
    const float* __restrict__ h0,    const float* __restrict__ c0) {

    int bid = blockIdx.x;
    int tid = threadIdx.x;

    if (bid < 2 * NCTA) {
        // ==================== recurrence (R12 verbatim + gating) =============
        int dir   = bid >> 6;
        int slice = bid & 63;
        int hbase = slice * HPER;
        const float* Whh = dir ? Whh_b : Whh_f;
        const float* Gd  = d_G[dir];
        float* hout = d_h[dir];
        int*   cnt  = d_cnt[dir];

        int w = tid >> 5;            // warp -> hidden unit u = hbase + w
        int lane = tid & 31;
        int u = hbase + w;
        int rep = slice & 7;

        // weights as f32x2 pairs
        u64 w2[4][8];
#pragma unroll
        for (int g = 0; g < 4; g++) {
            const u64* Wr = (const u64*)(Whh + (size_t)(g * H2 + u) * H2);
#pragma unroll
            for (int q = 0; q < 8; q++) w2[g][q] = Wr[q * 32 + lane];
        }

        __shared__ __align__(16) float sh[2][H2];

        float cj = c0[dir * H2 + u];

        // gate: chunk 0 must be complete before the G prologue
        if (tid == 0) { while (ld_acq_s32(&cnt[0]) < NBLK) { } }
        __syncthreads();

        // G prefetch pipeline, depth 2
        float gc0, gc1, gc2, gc3, gn0, gn1, gn2, gn3;
        {
            const float* Gt = Gd + u;
            gc0 = Gt[0]; gc1 = Gt[H2]; gc2 = Gt[2 * H2]; gc3 = Gt[3 * H2];
            const float* Gm = Gd + (size_t)G4 + u;
            gn0 = Gm[0]; gn1 = Gm[H2]; gn2 = Gm[2 * H2]; gn3 = Gm[3 * H2];
        }

        if (tid < 128)
            *(float4*)(sh[0] + tid * 4) = *(const float4*)(h0 + dir * H2 + tid * 4);
        __syncthreads();

        bool is_poller = (tid < 128) && ((tid >> 1) != slice);

        for (int t = 0; t < TT; t++) {
            // GEMV on sh[t&1], f32x2
            const u64* sh2 = (const u64*)(sh[t & 1]);
            u64 p0 = 0ull, p1 = 0ull, p2 = 0ull, p3 = 0ull;
#pragma unroll
            for (int q = 0; q < 8; q++) {
                u64 hv = sh2[q * 32 + lane];
                p0 = fma2(w2[0][q], hv, p0);
                p1 = fma2(w2[1][q], hv, p1);
                p2 = fma2(w2[2][q], hv, p2);
                p3 = fma2(w2[3][q], hv, p3);
            }
            float lo, hi;
            unpack2(p0, lo, hi); float a0 = lo + hi;
            unpack2(p1, lo, hi); float a1 = lo + hi;
            unpack2(p2, lo, hi); float a2 = lo + hi;
            unpack2(p3, lo, hi); float a3 = lo + hi;

            // gate + prefetch G(t+2)
            float gf0 = 0.f, gf1 = 0.f, gf2 = 0.f, gf3 = 0.f;
            if (t + 2 < TT) {
                if (((t + 2) & (CHUNK - 1)) == 0) {
                    int ch = (t + 2) >> 7;
                    if (tid == 0) { while (ld_acq_s32(&cnt[ch]) < NBLK) { } }
                    __syncthreads();
                }
                const float* Gf = Gd + (size_t)(t + 2) * G4 + u;
                gf0 = Gf[0]; gf1 = Gf[H2]; gf2 = Gf[2 * H2]; gf3 = Gf[3 * H2];
            }

            // butterfly all-reduce
#pragma unroll
            for (int off = 16; off > 0; off >>= 1) {
                a0 += __shfl_xor_sync(0xffffffffu, a0, off);
                a1 += __shfl_xor_sync(0xffffffffu, a1, off);
                a2 += __shfl_xor_sync(0xffffffffu, a2, off);
                a3 += __shfl_xor_sync(0xffffffffu, a3, off);
            }

            // redundant activation in all lanes
            float gi = a0 + gc0, gf = a1 + gc1, gg = a2 + gc2, go = a3 + gc3;
            cj = sigmoid_fast(gf) * cj + sigmoid_fast(gi) * tanh_fast(gg);
            float hj = sigmoid_fast(go) * tanh_fast(cj);

            // publish (h, tag=t) to the 8 replicas
            if (lane < NREP)
                st_rlx_pair(&d_sync[dir][lane][t & (SWIN - 1)][u * 2],
                            __float_as_uint(hj), (unsigned)t);
            if (lane == 8) hout[(size_t)t * H2 + u] = hj;
            if (lane == 0) sh[(t + 1) & 1][u] = hj;

            if (t + 1 < TT) {
                if (is_poller) {
                    const unsigned* p = &d_sync[dir][rep][t & (SWIN - 1)][tid * 8];
                    unsigned tt = (unsigned)t;
                    uint4 va, vb;
                    do {
                        va = ld_rlx_v4u(p);
                        vb = ld_rlx_v4u(p + 4);
                    } while (va.y != tt || va.w != tt || vb.y != tt || vb.w != tt);
                    float4 hv;
                    hv.x = __uint_as_float(va.x); hv.y = __uint_as_float(va.z);
                    hv.z = __uint_as_float(vb.x); hv.w = __uint_as_float(vb.z);
                    *(float4*)(sh[(t + 1) & 1] + tid * 4) = hv;
                }
                __syncthreads();
            }
            gc0 = gn0; gc1 = gn1; gc2 = gn2; gc3 = gn3;
            gn0 = gf0; gn1 = gf1; gn2 = gf2; gn3 = gf3;
        }
    } else {
        // ==================== GEMM tile (R12 k_gemm verbatim) ================
        int gidx = bid - 2 * NCTA;
        int nblk = gidx & 15;
        int dir  = (gidx >> 4) & 1;
        int tblk = gidx >> 5;                 // chunk-major: early t first
        const float* W  = dir ? Wih_b : Wih_f;
        const float* b1 = dir ? bih_b : bih_f;
        const float* b2 = dir ? bhh_b : bhh_f;
        float* Gp = d_G[dir];

        __shared__ float As[2][16 * 128];
        __shared__ float Bs[2][16 * 128];

        int m0 = tblk * CHUNK;
        int n0 = nblk * 128;
        int ty = tid >> 4, tx = tid & 15;

        int lrow[2], lkq[2];
        const float* Arow[2];
        const float* Brow[2];
#pragma unroll
        for (int h = 0; h < 2; h++) {
            int f = tid + h * 256;
            lrow[h] = f >> 2; lkq[h] = f & 3;
            int srcRow = m0 + lrow[h];
            if (dir) srcRow = TT - 1 - srcRow;
            int token = sent[srcRow];
            Arow[h] = embed + (size_t)token * EMB;
            Brow[h] = W + (size_t)(n0 + lrow[h]) * EMB;
        }

        float acc[8][8];
#pragma unroll
        for (int i = 0; i < 8; i++)
#pragma unroll
            for (int j = 0; j < 8; j++) acc[i][j] = 0.0f;

#pragma unroll
        for (int h = 0; h < 2; h++) {
            float4 va = *(const float4*)(Arow[h] + lkq[h] * 4);
            float4 vb = *(const float4*)(Brow[h] + lkq[h] * 4);
            As[0][(lkq[h]*4+0)*128 + lrow[h]] = va.x;
            As[0][(lkq[h]*4+1)*128 + lrow[h]] = va.y;
            As[0][(lkq[h]*4+2)*128 + lrow[h]] = va.z;
            As[0][(lkq[h]*4+3)*128 + lrow[h]] = va.w;
            Bs[0][(lkq[h]*4+0)*128 + lrow[h]] = vb.x;
            Bs[0][(lkq[h]*4+1)*128 + lrow[h]] = vb.y;
            Bs[0][(lkq[h]*4+2)*128 + lrow[h]] = vb.z;
            Bs[0][(lkq[h]*4+3)*128 + lrow[h]] = vb.w;
        }
        __syncthreads();

        for (int kt = 0; kt < EMB / 16; kt++) {
            int p = kt & 1;
            float4 va[2], vb[2];
            if (kt < EMB / 16 - 1) {
                int k0 = (kt + 1) * 16;
#pragma unroll
                for (int h = 0; h < 2; h++) {
                    va[h] = *(const float4*)(Arow[h] + k0 + lkq[h] * 4);
                    vb[h] = *(const float4*)(Brow[h] + k0 + lkq[h] * 4);
                }
            }
#pragma unroll
            for (int k = 0; k < 16; k++) {
                float a[8], bb[8];
#pragma unroll
                for (int i = 0; i < 8; i++) a[i]  = As[p][k * 128 + ty * 8 + i];
#pragma unroll
                for (int j = 0; j < 8; j++) bb[j] = Bs[p][k * 128 + tx * 8 + j];
#pragma unroll
                for (int i = 0; i < 8; i++)
#pragma unroll
                    for (int j = 0; j < 8; j++) acc[i][j] += a[i] * bb[j];
            }
            if (kt < EMB / 16 - 1) {
                int q = 1 - p;
                __syncthreads();
#pragma unroll
                for (int h = 0; h < 2; h++) {
                    As[q][(lkq[h]*4+0)*128 + lrow[h]] = va[h].x;
                    As[q][(lkq[h]*4+1)*128 + lrow[h]] = va[h].y;
                    As[q][(lkq[h]*4+2)*128 + lrow[h]] = va[h].z;
                    As[q][(lkq[h]*4+3)*128 + lrow[h]] = va[h].w;
                    Bs[q][(lkq[h]*4+0)*128 + lrow[h]] = vb[h].x;
                    Bs[q][(lkq[h]*4+1)*128 + lrow[h]] = vb[h].y;
                    Bs[q][(lkq[h]*4+2)*128 + lrow[h]] = vb[h].z;
                    Bs[q][(lkq[h]*4+3)*128 + lrow[h]] = vb[h].w;
                }
                __syncthreads();
            }
        }

        float bias[8];
#pragma unroll
        for (int j = 0; j < 8; j++) {
            int n = n0 + tx * 8 + j;
            bias[j] = b1[n] + b2[n];
        }
#pragma unroll
        for (int i = 0; i < 8; i++) {
            int m = m0 + ty * 8 + i;
#pragma unroll
            for (int j = 0; j < 8; j++) {
                int n = n0 + tx * 8 + j;
                Gp[(size_t)m * G4 + n] = acc[i][j] + bias[j];
            }
        }
        __threadfence();
        __syncthreads();
        if (tid == 0) red_rel_add(&d_cnt[dir][tblk]);
    }
}

// -------------------- kernel: output projection feats = [hf|hb] @ Wout^T ----
__global__ void k_feats(const float* __restrict__ Wout,
                        const float* __restrict__ bout) {
    int t = blockIdx.x;
    int n = threadIdx.x >> 5;              // 5 warps -> 5 tags
    int lane = threadIdx.x & 31;
    const float* hf = d_h[0] + (size_t)t * H2;
    const float* hb = d_h[1] + (size_t)(TT - 1 - t) * H2;
    float s = 0.0f;
    const float* Wn = Wout + (size_t)n * (2 * H2);
#pragma unroll 4
    for (int k = lane; k < H2; k += 32) s += Wn[k] * hf[k];
#pragma unroll 4
    for (int k = lane; k < H2; k += 32) s += Wn[H2 + k] * hb[k];
#pragma unroll
    for (int off = 16; off > 0; off >>= 1) s += __shfl_xor_sync(0xffffffffu, s, off);
    if (lane == 0) d_feats[t * 8 + n] = s + bout[n];
}

// -------------------- kernel: Viterbi + backtrace (single CTA) --------------
__global__ void k_viterbi(const float* __restrict__ trans,
                          float* __restrict__ out, int out_size) {
    extern __shared__ float smem[];
    float* sfeat = smem;                                    // TT*8 floats
    unsigned char* sbp = (unsigned char*)(smem + TT * 8);   // TT*8 bytes

    int tid = threadIdx.x;
    const float4* d4 = (const float4*)d_feats;
    float4* s4 = (float4*)sfeat;
    for (int i = tid; i < (TT * 8) / 4; i += blockDim.x) s4[i] = d4[i];
    __syncthreads();

    if (tid < 32) {
        int lane = tid;
        int n = lane < NTAGS ? lane : NTAGS - 1;
        float t00=trans[0], t01=trans[1], t02=trans[2], t03=trans[3], t04=trans[4];
        float t10=trans[5], t11=trans[6], t12=trans[7], t13=trans[8], t14=trans[9];
        float t20=trans[10],t21=trans[11],t22=trans[12],t23=trans[13],t24=trans[14];
        float t30=trans[15],t31=trans[16],t32=trans[17],t33=trans[18],t34=trans[19];
        float t40=trans[20],t41=trans[21],t42=trans[22],t43=trans[23],t44=trans[24];
        float trn0 = trans[n*5+0], trn1 = trans[n*5+1], trn2 = trans[n*5+2],
              trn3 = trans[n*5+3], trn4 = trans[n*5+4];

        float f0 = (0 == START) ? 0.0f : NEGV;
        float f1 = (1 == START) ? 0.0f : NEGV;
        float f2 = (2 == START) ? 0.0f : NEGV;
        float f3 = (3 == START) ? 0.0f : NEGV;
        float f4 = (4 == START) ? 0.0f : NEGV;

        float4 ft = *(const float4*)(sfeat);
        float ft4 = sfeat[4];

        for (int t = 0; t < TT; t++) {
            float4 ftn; float ftn4 = 0.0f;
            ftn.x = ftn.y = ftn.z = ftn.w = 0.0f;
            if (t + 1 < TT) {
                ftn = *(const float4*)(sfeat + (t + 1) * 8);
                ftn4 = sfeat[(t + 1) * 8 + 4];
            }

            float b = f0 + trn0; int bp = 0; float v;
            v = f1 + trn1; if (v > b) { b = v; bp = 1; }
            v = f2 + trn2; if (v > b) { b = v; bp = 2; }
            v = f3 + trn3; if (v > b) { b = v; bp = 3; }
            v = f4 + trn4; if (v > b) { b = v; bp = 4; }
            if (lane < NTAGS) sbp[t * 8 + lane] = (unsigned char)bp;

            float m0 = fmaxf(fmaxf(fmaxf(f0+t00, f1+t01), fmaxf(f2+t02, f3+t03)), f4+t04);
            float m1 = fmaxf(fmaxf(fmaxf(f0+t10, f1+t11), fmaxf(f2+t12, f3+t13)), f4+t14);
            float m2 = fmaxf(fmaxf(fmaxf(f0+t20, f1+t21), fmaxf(f2+t22, f3+t23)), f4+t24);
            float m3 = fmaxf(fmaxf(fmaxf(f0+t30, f1+t31), fmaxf(f2+t32, f3+t33)), f4+t34);
            float m4 = fmaxf(fmaxf(fmaxf(f0+t40, f1+t41), fmaxf(f2+t42, f3+t43)), f4+t44);
            f0 = m0 + ft.x; f1 = m1 + ft.y; f2 = m2 + ft.z; f3 = m3 + ft.w; f4 = m4 + ft4;

            ft = ftn; ft4 = ftn4;
        }

        if (lane == 0) {
            float fv[NTAGS] = {f0, f1, f2, f3, f4};
            float best = fv[0] + trans[STOP * NTAGS + 0];
            int bt = 0;
#pragma unroll
            for (int p = 1; p < NTAGS; p++) {
                float s = fv[p] + trans[STOP * NTAGS + p];
                if (s > best) { best = s; bt = p; }
            }
            if (out_size > 0) out[0] = best;
            int tag = bt;
            if (1 + (TT - 1) < out_size) out[1 + (TT - 1)] = (float)tag;
            for (int t = TT - 1; t >= 1; t--) {
                tag = sbp[t * 8 + tag];
                if (t < out_size) out[t] = (float)tag;
            }
        }
    }
}

// -------------------- launcher ----------------------------------------------
extern "C" void kernel_launch(void* const* d_in, const int* in_sizes, int n_in,
                              void* d_out, int out_size) {
    const int*   sent  = (const int*)d_in[0];
    const float* h0    = (const float*)d_in[1];
    const float* c0    = (const float*)d_in[2];
    const float* embed = (const float*)d_in[3];
    const float* Wih_f = (const float*)d_in[4];
    const float* Whh_f = (const float*)d_in[5];
    const float* bih_f = (const float*)d_in[6];
    const float* bhh_f = (const float*)d_in[7];
    const float* Wih_b = (const float*)d_in[8];
    const float* Whh_b = (const float*)d_in[9];
    const float* bih_b = (const float*)d_in[10];
    const float* bhh_b = (const float*)d_in[11];
    const float* Wout  = (const float*)d_in[12];
    const float* bout  = (const float*)d_in[13];
    const float* trans = (const float*)d_in[14];
    float* out = (float*)d_out;

    k_init<<<64, 512>>>();
    int nblocks = 2 * NCTA + NCHUNK * NBLK * 2;   // 128 + 1024 = 1152
    k_main<<<nblocks, 256>>>(sent, embed,
                             Wih_f, Whh_f, bih_f, bhh_f,
                             Wih_b, Whh_b, bih_b, bhh_b, h0, c0);
    k_feats<<<TT, 160>>>(Wout, bout);

    int vit_smem = TT * 8 * (int)sizeof(float) + TT * 8;   // 163840 B
    cudaFuncSetAttribute(k_viterbi, cudaFuncAttributeMaxDynamicSharedMemorySize,
                         vit_smem);
    k_viterbi<<<1, 128, vit_smem>>>(trans, out, out_size);
}

// round 14
// speedup vs baseline: 1.0478x; 1.0478x over previous
#include <cuda_runtime.h>

// Problem constants
#define TT    4096
#define EMB   1024
#define H2    512
#define G4    2048       // 4 * H2
#define NTAGS 5
#define START 3
#define STOP  4
#define NEGV  -10000.0f

// Recurrence: 64 CTAs per direction, 8 hidden units each (R12 structure)
#define NCTA   64
#define HPER   8
#define NREP   16        // sync replication factor (poll-traffic spreading)
#define SWIN   8         // sync ring depth (slot = t & 7)

typedef unsigned long long u64;

// -------------------- scratch (static device globals; no allocs) ------------
__device__ float d_G[2][TT * G4];               // input preactivations (64 MB)
__device__ float d_h[2][TT * H2];               // hidden history for feats (16 MB)
__device__ unsigned d_sync[2][NREP][SWIN][H2 * 2];  // (h,tag) pairs — 1 MB, L2-hot
__device__ float d_feats[TT * 8];               // tag scores, stride 8

// -------------------- helpers ----------------------------------------------
__device__ __forceinline__ uint4 ld_rlx_v4u(const unsigned* p) {
    uint4 v;
    asm volatile("ld.relaxed.gpu.global.v4.u32 {%0,%1,%2,%3}, [%4];"
                 : "=r"(v.x), "=r"(v.y), "=r"(v.z), "=r"(v.w) : "l"(p) : "memory");
    return v;
}
__device__ __forceinline__ void st_rlx_pair(unsigned* p, unsigned hbits, unsigned tag) {
    unsigned long long v = ((unsigned long long)tag << 32) | (unsigned long long)hbits;
    asm volatile("st.relaxed.gpu.global.b64 [%0], %1;" :: "l"(p), "l"(v) : "memory");
}
__device__ __forceinline__ float tanh_fast(float x) {
    float y;
    asm("tanh.approx.f32 %0, %1;" : "=f"(y) : "f"(x));
    return y;
}
__device__ __forceinline__ float sigmoid_fast(float x) {
    return fmaf(0.5f, tanh_fast(0.5f * x), 0.5f);
}
__device__ __forceinline__ u64 fma2(u64 a, u64 b, u64 c) {
    u64 d;
    asm("fma.rn.f32x2 %0, %1, %2, %3;" : "=l"(d) : "l"(a), "l"(b), "l"(c));
    return d;
}
__device__ __forceinline__ void unpack2(u64 v, float& lo, float& hi) {
    asm("mov.b64 {%0, %1}, %2;" : "=f"(lo), "=f"(hi) : "l"(v));
}

// -------------------- kernel: init sync ring tags ----------------------------
// d_sync = 2*16*8*1024 uints = 262144 uints = 65536 uint4
__global__ void k_init() {
    int i = blockIdx.x * blockDim.x + threadIdx.x;
    uint4 s; s.x = 0xFFFFFFFFu; s.y = 0xFFFFFFFFu; s.z = 0xFFFFFFFFu; s.w = 0xFFFFFFFFu;
    if (i < 65536) ((uint4*)d_sync)[i] = s;
}

// -------------------- kernel: input GEMM  G = embed[sent] @ Wih^T + bias ----
// C tile 128x128, K tile 16, 256 threads, 8x8 blocking, double-buffered smem,
// embedding gather fused into the A load. dir==1 reads tokens in reverse.
__global__ __launch_bounds__(256) void k_gemm(
    const int*   __restrict__ sent, const float* __restrict__ embed,
    const float* __restrict__ Wf, const float* __restrict__ Wb,
    const float* __restrict__ bihf, const float* __restrict__ bhhf,
    const float* __restrict__ bihb, const float* __restrict__ bhhb) {
    int dir = blockIdx.z;
    const float* W  = dir ? Wb   : Wf;
    const float* b1 = dir ? bihb : bihf;
    const float* b2 = dir ? bhhb : bhhf;
    float* Gp = d_G[dir];

    __shared__ float As[2][16 * 128];
    __shared__ float Bs[2][16 * 128];

    int tid = threadIdx.x;
    int m0 = blockIdx.y * 128;
    int n0 = blockIdx.x * 128;
    int ty = tid >> 4, tx = tid & 15;

    int lrow[2], lkq[2];
    const float* Arow[2];
    const float* Brow[2];
#pragma unroll
    for (int h = 0; h < 2; h++) {
        int f = tid + h * 256;
        lrow[h] = f >> 2; lkq[h] = f & 3;
        int srcRow = m0 + lrow[h];
        if (dir) srcRow = TT - 1 - srcRow;
        int token = sent[srcRow];
        Arow[h] = embed + (size_t)token * EMB;
        Brow[h] = W + (size_t)(n0 + lrow[h]) * EMB;
    }

    float acc[8][8];
#pragma unroll
    for (int i = 0; i < 8; i++)
#pragma unroll
        for (int j = 0; j < 8; j++) acc[i][j] = 0.0f;

#pragma unroll
    for (int h = 0; h < 2; h++) {
        float4 va = *(const float4*)(Arow[h] + lkq[h] * 4);
        float4 vb = *(const float4*)(Brow[h] + lkq[h] * 4);
        As[0][(lkq[h]*4+0)*128 + lrow[h]] = va.x;
        As[0][(lkq[h]*4+1)*128 + lrow[h]] = va.y;
        As[0][(lkq[h]*4+2)*128 + lrow[h]] = va.z;
        As[0][(lkq[h]*4+3)*128 + lrow[h]] = va.w;
        Bs[0][(lkq[h]*4+0)*128 + lrow[h]] = vb.x;
        Bs[0][(lkq[h]*4+1)*128 + lrow[h]] = vb.y;
        Bs[0][(lkq[h]*4+2)*128 + lrow[h]] = vb.z;
        Bs[0][(lkq[h]*4+3)*128 + lrow[h]] = vb.w;
    }
    __syncthreads();

    for (int kt = 0; kt < EMB / 16; kt++) {
        int p = kt & 1;
        float4 va[2], vb[2];
        if (kt < EMB / 16 - 1) {
            int k0 = (kt + 1) * 16;
#pragma unroll
            for (int h = 0; h < 2; h++) {
                va[h] = *(const float4*)(Arow[h] + k0 + lkq[h] * 4);
                vb[h] = *(const float4*)(Brow[h] + k0 + lkq[h] * 4);
            }
        }
#pragma unroll
        for (int k = 0; k < 16; k++) {
            float a[8], bb[8];
#pragma unroll
            for (int i = 0; i < 8; i++) a[i]  = As[p][k * 128 + ty * 8 + i];
#pragma unroll
            for (int j = 0; j < 8; j++) bb[j] = Bs[p][k * 128 + tx * 8 + j];
#pragma unroll
            for (int i = 0; i < 8; i++)
#pragma unroll
                for (int j = 0; j < 8; j++) acc[i][j] += a[i] * bb[j];
        }
        if (kt < EMB / 16 - 1) {
            int q = 1 - p;
            __syncthreads();
#pragma unroll
            for (int h = 0; h < 2; h++) {
                As[q][(lkq[h]*4+0)*128 + lrow[h]] = va[h].x;
                As[q][(lkq[h]*4+1)*128 + lrow[h]] = va[h].y;
                As[q][(lkq[h]*4+2)*128 + lrow[h]] = va[h].z;
                As[q][(lkq[h]*4+3)*128 + lrow[h]] = va[h].w;
                Bs[q][(lkq[h]*4+0)*128 + lrow[h]] = vb[h].x;
                Bs[q][(lkq[h]*4+1)*128 + lrow[h]] = vb[h].y;
                Bs[q][(lkq[h]*4+2)*128 + lrow[h]] = vb[h].z;
                Bs[q][(lkq[h]*4+3)*128 + lrow[h]] = vb[h].w;
            }
            __syncthreads();
        }
    }

    float bias[8];
#pragma unroll
    for (int j = 0; j < 8; j++) {
        int n = n0 + tx * 8 + j;
        bias[j] = b1[n] + b2[n];
    }
#pragma unroll
    for (int i = 0; i < 8; i++) {
        int m = m0 + ty * 8 + i;
#pragma unroll
        for (int j = 0; j < 8; j++) {
            int n = n0 + tx * 8 + j;
            Gp[(size_t)m * G4 + n] = acc[i][j] + bias[j];
        }
    }
}

// -------------------- kernel: persistent LSTM recurrence --------------------
// 128 CTAs (64/dir), 256 threads = 8 warps; warp w owns hidden unit hbase+w.
// R12 structure; poll refined: ALL 256 threads poll ONE v4 (2 h elems) each.
__global__ void __launch_bounds__(256, 1) k_recur(
    const float* __restrict__ Whh_f, const float* __restrict__ Whh_b,
    const float* __restrict__ h0, const float* __restrict__ c0) {
    int dir   = blockIdx.x >> 6;
    int slice = blockIdx.x & 63;
    int hbase = slice * HPER;
    const float* Whh = dir ? Whh_b : Whh_f;
    const float* Gd  = d_G[dir];
    float* hout = d_h[dir];

    int tid = threadIdx.x;
    int w = tid >> 5;            // warp -> hidden unit u = hbase + w
    int lane = tid & 31;
    int u = hbase + w;
    int rep = slice & (NREP - 1);

    // weights as f32x2 pairs: pair q of gate g = Whh[row*H2 + q*64 + lane*2 ..+1]
    u64 w2[4][8];
#pragma unroll
    for (int g = 0; g < 4; g++) {
        const u64* Wr = (const u64*)(Whh + (size_t)(g * H2 + u) * H2);
#pragma unroll
        for (int q = 0; q < 8; q++) w2[g][q] = Wr[q * 32 + lane];
    }

    __shared__ __align__(16) float sh[2][H2];

    float cj = c0[dir * H2 + u];             // identical in all lanes

    // G prefetch pipeline, depth 2 (G is a DRAM stream)
    float gc0, gc1, gc2, gc3;                // step t
    float gn0, gn1, gn2, gn3;                // step t+1
    {
        const float* Gt = Gd + u;
        gc0 = Gt[0]; gc1 = Gt[H2]; gc2 = Gt[2 * H2]; gc3 = Gt[3 * H2];
        const float* Gm = Gd + (size_t)G4 + u;
        gn0 = Gm[0]; gn1 = Gm[H2]; gn2 = Gm[2 * H2]; gn3 = Gm[3 * H2];
    }

    // stage h(-1) = h0 (no polling)
    if (tid < 128)
        *(float4*)(sh[0] + tid * 4) = *(const float4*)(h0 + dir * H2 + tid * 4);
    __syncthreads();

    // poller tid covers h elems [tid*2, tid*2+2); own slice = [slice*8,+8)
    bool is_poller = ((tid >> 2) != slice);

    for (int t = 0; t < TT; t++) {
        // GEMV on sh[t&1], f32x2: 32 FFMA2 per lane
        const u64* sh2 = (const u64*)(sh[t & 1]);
        u64 p0 = 0ull, p1 = 0ull, p2 = 0ull, p3 = 0ull;
#pragma unroll
        for (int q = 0; q < 8; q++) {
            u64 hv = sh2[q * 32 + lane];
            p0 = fma2(w2[0][q], hv, p0);
            p1 = fma2(w2[1][q], hv, p1);
            p2 = fma2(w2[2][q], hv, p2);
            p3 = fma2(w2[3][q], hv, p3);
        }
        float lo, hi;
        unpack2(p0, lo, hi); float a0 = lo + hi;
        unpack2(p1, lo, hi); float a1 = lo + hi;
        unpack2(p2, lo, hi); float a2 = lo + hi;
        unpack2(p3, lo, hi); float a3 = lo + hi;

        // issue G(t+2) prefetch early (2 steps of cover for DRAM latency)
        float gf0 = 0.f, gf1 = 0.f, gf2 = 0.f, gf3 = 0.f;
        if (t + 2 < TT) {
            const float* Gf = Gd + (size_t)(t + 2) * G4 + u;
            gf0 = Gf[0]; gf1 = Gf[H2]; gf2 = Gf[2 * H2]; gf3 = Gf[3 * H2];
        }

        // butterfly all-reduce (gate sums land in every lane)
#pragma unroll
        for (int off = 16; off > 0; off >>= 1) {
            a0 += __shfl_xor_sync(0xffffffffu, a0, off);
            a1 += __shfl_xor_sync(0xffffffffu, a1, off);
            a2 += __shfl_xor_sync(0xffffffffu, a2, off);
            a3 += __shfl_xor_sync(0xffffffffu, a3, off);
        }

        // redundant activation in all lanes
        float gi = a0 + gc0, gf = a1 + gc1, gg = a2 + gc2, go = a3 + gc3;
        cj = sigmoid_fast(gf) * cj + sigmoid_fast(gi) * tanh_fast(gg);
        float hj = sigmoid_fast(go) * tanh_fast(cj);

        // publish (h, tag=t) atomically to the NREP replicas (lanes 0-15)
        if (lane < NREP)
            st_rlx_pair(&d_sync[dir][lane][t & (SWIN - 1)][u * 2],
                        __float_as_uint(hj), (unsigned)t);
        // history write for k_feats (lane 16), own-unit pre-stage (lane 0)
        if (lane == 16) hout[(size_t)t * H2 + u] = hj;
        if (lane == 0) sh[(t + 1) & 1][u] = hj;

        if (t + 1 < TT) {
            // poll: each thread fetches its 2 h elems (one v4 of pairs)
            if (is_poller) {
                const unsigned* p = &d_sync[dir][rep][t & (SWIN - 1)][tid * 4];
                unsigned tt = (unsigned)t;
                uint4 va;
                do { va = ld_rlx_v4u(p); } while (va.y != tt || va.w != tt);
                float2 hv;
                hv.x = __uint_as_float(va.x); hv.y = __uint_as_float(va.z);
                *(float2*)(sh[(t + 1) & 1] + tid * 2) = hv;
            }
            __syncthreads();
        }
        gc0 = gn0; gc1 = gn1; gc2 = gn2; gc3 = gn3;
        gn0 = gf0; gn1 = gf1; gn2 = gf2; gn3 = gf3;
    }
}

// -------------------- kernel: output projection feats = [hf|hb] @ Wout^T ----
__global__ void k_feats(const float* __restrict__ Wout,
                        const float* __restrict__ bout) {
    int t = blockIdx.x;
    int n = threadIdx.x >> 5;              // 5 warps -> 5 tags
    int lane = threadIdx.x & 31;
    const float* hf = d_h[0] + (size_t)t * H2;
    const float* hb = d_h[1] + (size_t)(TT - 1 - t) * H2;
    float s = 0.0f;
    const float* Wn = Wout + (size_t)n * (2 * H2);
#pragma unroll 4
    for (int k = lane; k < H2; k += 32) s += Wn[k] * hf[k];
#pragma unroll 4
    for (int k = lane; k < H2; k += 32) s += Wn[H2 + k] * hb[k];
#pragma unroll
    for (int off = 16; off > 0; off >>= 1) s += __shfl_xor_sync(0xffffffffu, s, off);
    if (lane == 0) d_feats[t * 8 + n] = s + bout[n];
}

// -------------------- kernel: Viterbi + backtrace (single CTA) --------------
// Lanes 0-4 hold the full forward vector in registers; backpointer computed by
// parallel equality against the fmaxf-tree max (no predicated serial chain).
__global__ void k_viterbi(const float* __restrict__ trans,
                          float* __restrict__ out, int out_size) {
    extern __shared__ float smem[];
    float* sfeat = smem;                                    // TT*8 floats
    unsigned char* sbp = (unsigned char*)(smem + TT * 8);   // TT*8 bytes

    int tid = threadIdx.x;
    const float4* d4 = (const float4*)d_feats;
    float4* s4 = (float4*)sfeat;
    for (int i = tid; i < (TT * 8) / 4; i += blockDim.x) s4[i] = d4[i];
    __syncthreads();

    if (tid < 32) {
        int lane = tid;
        float t00=trans[0], t01=trans[1], t02=trans[2], t03=trans[3], t04=trans[4];
        float t10=trans[5], t11=trans[6], t12=trans[7], t13=trans[8], t14=trans[9];
        float t20=trans[10],t21=trans[11],t22=trans[12],t23=trans[13],t24=trans[14];
        float t30=trans[15],t31=trans[16],t32=trans[17],t33=trans[18],t34=trans[19];
        float t40=trans[20],t41=trans[21],t42=trans[22],t43=trans[23],t44=trans[24];

        float f0 = (0 == START) ? 0.0f : NEGV;
        float f1 = (1 == START) ? 0.0f : NEGV;
        float f2 = (2 == START) ? 0.0f : NEGV;
        float f3 = (3 == START) ? 0.0f : NEGV;
        float f4 = (4 == START) ? 0.0f : NEGV;

        float4 ft = *(const float4*)(sfeat);
        float ft4 = sfeat[4];

        for (int t = 0; t < TT; t++) {
            float4 ftn; float ftn4 = 0.0f;
            ftn.x = ftn.y = ftn.z = ftn.w = 0.0f;
            if (t + 1 < TT) {
                ftn = *(const float4*)(sfeat + (t + 1) * 8);
                ftn4 = sfeat[(t + 1) * 8 + 4];
            }

            // candidates (parallel FADDs, reused for max and backpointer)
            float c00=f0+t00, c01=f1+t01, c02=f2+t02, c03=f3+t03, c04=f4+t04;
            float c10=f0+t10, c11=f1+t11, c12=f2+t12, c13=f3+t13, c14=f4+t14;
            float c20=f0+t20, c21=f1+t21, c22=f2+t22, c23=f3+t23, c24=f4+t24;
            float c30=f0+t30, c31=f1+t31, c32=f2+t32, c33=f3+t33, c34=f4+t34;
            float c40=f0+t40, c41=f1+t41, c42=f2+t42, c43=f3+t43, c44=f4+t44;

            float m0 = fmaxf(fmaxf(fmaxf(c00,c01), fmaxf(c02,c03)), c04);
            float m1 = fmaxf(fmaxf(fmaxf(c10,c11), fmaxf(c12,c13)), c14);
            float m2 = fmaxf(fmaxf(fmaxf(c20,c21), fmaxf(c22,c23)), c24);
            float m3 = fmaxf(fmaxf(fmaxf(c30,c31), fmaxf(c32,c33)), c34);
            float m4 = fmaxf(fmaxf(fmaxf(c40,c41), fmaxf(c42,c43)), c44);

            // backpointers: first candidate equal to the max (bit-exact);
            // lanes 0-4 each store one tag's bp (parallel equality, SEL cascade)
            if (lane < NTAGS) {
                float mn, d0, d1, d2, d3, d4;
                switch (lane) {
                    case 0: mn=m0; d0=c00; d1=c01; d2=c02; d3=c03; d4=c04; break;
                    case 1: mn=m1; d0=c10; d1=c11; d2=c12; d3=c13; d4=c14; break;
                    case 2: mn=m2; d0=c20; d1=c21; d2=c22; d3=c23; d4=c24; break;
                    case 3: mn=m3; d0=c30; d1=c31; d2=c32; d3=c33; d4=c34; break;
                    default: mn=m4; d0=c40; d1=c41; d2=c42; d3=c43; d4=c44; break;
                }
                int bp = (d0 == mn) ? 0 : (d1 == mn) ? 1 : (d2 == mn) ? 2
                        : (d3 == mn) ? 3 : 4;
                sbp[t * 8 + lane] = (unsigned char)bp;
            }

            f0 = m0 + ft.x; f1 = m1 + ft.y; f2 = m2 + ft.z; f3 = m3 + ft.w; f4 = m4 + ft4;
            ft = ftn; ft4 = ftn4;
        }

        if (lane == 0) {
            float fv[NTAGS] = {f0, f1, f2, f3, f4};
            float best = fv[0] + trans[STOP * NTAGS + 0];
            int bt = 0;
#pragma unroll
            for (int p = 1; p < NTAGS; p++) {
                float s = fv[p] + trans[STOP * NTAGS + p];
                if (s > best) { best = s; bt = p; }
            }
            if (out_size > 0) out[0] = best;
            int tag = bt;
            if (1 + (TT - 1) < out_size) out[1 + (TT - 1)] = (float)tag;
            for (int t = TT - 1; t >= 1; t--) {
                tag = sbp[t * 8 + tag];
                if (t < out_size) out[t] = (float)tag;
            }
        }
    }
}

// -------------------- launcher ----------------------------------------------
extern "C" void kernel_launch(void* const* d_in, const int* in_sizes, int n_in,
                              void* d_out, int out_size) {
    const int*   sent  = (const int*)d_in[0];
    const float* h0    = (const float*)d_in[1];
    const float* c0    = (const float*)d_in[2];
    const float* embed = (const float*)d_in[3];
    const float* Wih_f = (const float*)d_in[4];
    const float* Whh_f = (const float*)d_in[5];
    const float* bih_f = (const float*)d_in[6];
    const float* bhh_f = (const float*)d_in[7];
    const float* Wih_b = (const float*)d_in[8];
    const float* Whh_b = (const float*)d_in[9];
    const float* bih_b = (const float*)d_in[10];
    const float* bhh_b = (const float*)d_in[11];
    const float* Wout  = (const float*)d_in[12];
    const float* bout  = (const float*)d_in[13];
    const float* trans = (const float*)d_in[14];
    float* out = (float*)d_out;

    k_init<<<128, 512>>>();
    dim3 gg(G4 / 128, TT / 128, 2);
    k_gemm<<<gg, 256>>>(sent, embed, Wih_f, Wih_b,
                        bih_f, bhh_f, bih_b, bhh_b);
    k_recur<<<2 * NCTA, 256>>>(Whh_f, Whh_b, h0, c0);
    k_feats<<<TT, 160>>>(Wout, bout);

    int vit_smem = TT * 8 * (int)sizeof(float) + TT * 8;   // 163840 B
    cudaFuncSetAttribute(k_viterbi, cudaFuncAttributeMaxDynamicSharedMemorySize,
                         vit_smem);
    k_viterbi<<<1, 128, vit_smem>>>(trans, out, out_size);
}

// round 15
// speedup vs baseline: 1.1204x; 1.0693x over previous
#include <cuda_runtime.h>

// Problem constants
#define TT    4096
#define EMB   1024
#define H2    512
#define G4    2048       // 4 * H2
#define NTAGS 5
#define START 3
#define STOP  4
#define NEGV  -10000.0f

// Recurrence: 64 CTAs per direction, 8 hidden units each (R12 structure)
#define NCTA   64
#define HPER   8
#define NREP   8         // sync replication factor (poll-traffic spreading)
#define SWIN   8         // sync ring depth (slot = t & 7)

typedef unsigned long long u64;

// -------------------- scratch (static device globals; no allocs) ------------
__device__ float d_G[2][TT * G4];               // input preactivations (64 MB)
__device__ float d_h[2][TT * H2];               // hidden history for feats (16 MB)
__device__ unsigned d_sync[2][NREP][SWIN][H2 * 2];  // (h,tag) pairs — 512 KB, L2-hot
__device__ float d_feats[TT * 8];               // tag scores, stride 8

// -------------------- helpers ----------------------------------------------
__device__ __forceinline__ uint4 ld_rlx_v4u(const unsigned* p) {
    uint4 v;
    asm volatile("ld.relaxed.gpu.global.v4.u32 {%0,%1,%2,%3}, [%4];"
                 : "=r"(v.x), "=r"(v.y), "=r"(v.z), "=r"(v.w) : "l"(p) : "memory");
    return v;
}
__device__ __forceinline__ void st_rlx_pair(unsigned* p, unsigned hbits, unsigned tag) {
    unsigned long long v = ((unsigned long long)tag << 32) | (unsigned long long)hbits;
    asm volatile("st.relaxed.gpu.global.b64 [%0], %1;" :: "l"(p), "l"(v) : "memory");
}
__device__ __forceinline__ float tanh_fast(float x) {
    float y;
    asm("tanh.approx.f32 %0, %1;" : "=f"(y) : "f"(x));
    return y;
}
__device__ __forceinline__ float sigmoid_fast(float x) {
    return fmaf(0.5f, tanh_fast(0.5f * x), 0.5f);
}
__device__ __forceinline__ u64 fma2(u64 a, u64 b, u64 c) {
    u64 d;
    asm("fma.rn.f32x2 %0, %1, %2, %3;" : "=l"(d) : "l"(a), "l"(b), "l"(c));
    return d;
}
__device__ __forceinline__ void unpack2(u64 v, float& lo, float& hi) {
    asm("mov.b64 {%0, %1}, %2;" : "=f"(lo), "=f"(hi) : "l"(v));
}

// -------------------- kernel: init sync ring tags ----------------------------
// d_sync = 2*8*8*1024 uints = 131072 uints = 32768 uint4
__global__ void k_init() {
    int i = blockIdx.x * blockDim.x + threadIdx.x;
    uint4 s; s.x = 0xFFFFFFFFu; s.y = 0xFFFFFFFFu; s.z = 0xFFFFFFFFu; s.w = 0xFFFFFFFFu;
    if (i < 32768) ((uint4*)d_sync)[i] = s;
}

// -------------------- kernel: input GEMM  G = embed[sent] @ Wih^T + bias ----
// C tile 128x128, K tile 16, 256 threads, 8x8 blocking, double-buffered smem,
// embedding gather fused into the A load. dir==1 reads tokens in reverse.
__global__ __launch_bounds__(256) void k_gemm(
    const int*   __restrict__ sent, const float* __restrict__ embed,
    const float* __restrict__ Wf, const float* __restrict__ Wb,
    const float* __restrict__ bihf, const float* __restrict__ bhhf,
    const float* __restrict__ bihb, const float* __restrict__ bhhb) {
    int dir = blockIdx.z;
    const float* W  = dir ? Wb   : Wf;
    const float* b1 = dir ? bihb : bihf;
    const float* b2 = dir ? bhhb : bhhf;
    float* Gp = d_G[dir];

    __shared__ float As[2][16 * 128];
    __shared__ float Bs[2][16 * 128];

    int tid = threadIdx.x;
    int m0 = blockIdx.y * 128;
    int n0 = blockIdx.x * 128;
    int ty = tid >> 4, tx = tid & 15;

    int lrow[2], lkq[2];
    const float* Arow[2];
    const float* Brow[2];
#pragma unroll
    for (int h = 0; h < 2; h++) {
        int f = tid + h * 256;
        lrow[h] = f >> 2; lkq[h] = f & 3;
        int srcRow = m0 + lrow[h];
        if (dir) srcRow = TT - 1 - srcRow;
        int token = sent[srcRow];
        Arow[h] = embed + (size_t)token * EMB;
        Brow[h] = W + (size_t)(n0 + lrow[h]) * EMB;
    }

    float acc[8][8];
#pragma unroll
    for (int i = 0; i < 8; i++)
#pragma unroll
        for (int j = 0; j < 8; j++) acc[i][j] = 0.0f;

#pragma unroll
    for (int h = 0; h < 2; h++) {
        float4 va = *(const float4*)(Arow[h] + lkq[h] * 4);
        float4 vb = *(const float4*)(Brow[h] + lkq[h] * 4);
        As[0][(lkq[h]*4+0)*128 + lrow[h]] = va.x;
        As[0][(lkq[h]*4+1)*128 + lrow[h]] = va.y;
        As[0][(lkq[h]*4+2)*128 + lrow[h]] = va.z;
        As[0][(lkq[h]*4+3)*128 + lrow[h]] = va.w;
        Bs[0][(lkq[h]*4+0)*128 + lrow[h]] = vb.x;
        Bs[0][(lkq[h]*4+1)*128 + lrow[h]] = vb.y;
        Bs[0][(lkq[h]*4+2)*128 + lrow[h]] = vb.z;
        Bs[0][(lkq[h]*4+3)*128 + lrow[h]] = vb.w;
    }
    __syncthreads();

    for (int kt = 0; kt < EMB / 16; kt++) {
        int p = kt & 1;
        float4 va[2], vb[2];
        if (kt < EMB / 16 - 1) {
            int k0 = (kt + 1) * 16;
#pragma unroll
            for (int h = 0; h < 2; h++) {
                va[h] = *(const float4*)(Arow[h] + k0 + lkq[h] * 4);
                vb[h] = *(const float4*)(Brow[h] + k0 + lkq[h] * 4);
            }
        }
#pragma unroll
        for (int k = 0; k < 16; k++) {
            float a[8], bb[8];
#pragma unroll
            for (int i = 0; i < 8; i++) a[i]  = As[p][k * 128 + ty * 8 + i];
#pragma unroll
            for (int j = 0; j < 8; j++) bb[j] = Bs[p][k * 128 + tx * 8 + j];
#pragma unroll
            for (int i = 0; i < 8; i++)
#pragma unroll
                for (int j = 0; j < 8; j++) acc[i][j] += a[i] * bb[j];
        }
        if (kt < EMB / 16 - 1) {
            int q = 1 - p;
            __syncthreads();
#pragma unroll
            for (int h = 0; h < 2; h++) {
                As[q][(lkq[h]*4+0)*128 + lrow[h]] = va[h].x;
                As[q][(lkq[h]*4+1)*128 + lrow[h]] = va[h].y;
                As[q][(lkq[h]*4+2)*128 + lrow[h]] = va[h].z;
                As[q][(lkq[h]*4+3)*128 + lrow[h]] = va[h].w;
                Bs[q][(lkq[h]*4+0)*128 + lrow[h]] = vb[h].x;
                Bs[q][(lkq[h]*4+1)*128 + lrow[h]] = vb[h].y;
                Bs[q][(lkq[h]*4+2)*128 + lrow[h]] = vb[h].z;
                Bs[q][(lkq[h]*4+3)*128 + lrow[h]] = vb[h].w;
            }
            __syncthreads();
        }
    }

    float bias[8];
#pragma unroll
    for (int j = 0; j < 8; j++) {
        int n = n0 + tx * 8 + j;
        bias[j] = b1[n] + b2[n];
    }
#pragma unroll
    for (int i = 0; i < 8; i++) {
        int m = m0 + ty * 8 + i;
#pragma unroll
        for (int j = 0; j < 8; j++) {
            int n = n0 + tx * 8 + j;
            Gp[(size_t)m * G4 + n] = acc[i][j] + bias[j];
        }
    }
}

// -------------------- kernel: persistent LSTM recurrence --------------------
// 128 CTAs (64/dir), 256 threads = 8 warps; warp w owns hidden unit hbase+w.
// R12 verbatim: staged poll (tid<128, two v4 loads) + ONE __syncthreads/step;
// sync via 512KB L2-resident (h,tag) ring; GEMV in f32x2.
__global__ void __launch_bounds__(256, 1) k_recur(
    const float* __restrict__ Whh_f, const float* __restrict__ Whh_b,
    const float* __restrict__ h0, const float* __restrict__ c0) {
    int dir   = blockIdx.x >> 6;
    int slice = blockIdx.x & 63;
    int hbase = slice * HPER;
    const float* Whh = dir ? Whh_b : Whh_f;
    const float* Gd  = d_G[dir];
    float* hout = d_h[dir];

    int tid = threadIdx.x;
    int w = tid >> 5;            // warp -> hidden unit u = hbase + w
    int lane = tid & 31;
    int u = hbase + w;
    int rep = slice & 7;         // which replica this CTA polls

    // weights as f32x2 pairs: pair q of gate g = Whh[row*H2 + q*64 + lane*2 ..+1]
    u64 w2[4][8];
#pragma unroll
    for (int g = 0; g < 4; g++) {
        const u64* Wr = (const u64*)(Whh + (size_t)(g * H2 + u) * H2);
#pragma unroll
        for (int q = 0; q < 8; q++) w2[g][q] = Wr[q * 32 + lane];
    }

    __shared__ __align__(16) float sh[2][H2];

    float cj = c0[dir * H2 + u];             // identical in all lanes

    // G prefetch pipeline, depth 2 (G is a DRAM stream)
    float gc0, gc1, gc2, gc3;                // step t
    float gn0, gn1, gn2, gn3;                // step t+1
    {
        const float* Gt = Gd + u;
        gc0 = Gt[0]; gc1 = Gt[H2]; gc2 = Gt[2 * H2]; gc3 = Gt[3 * H2];
        const float* Gm = Gd + (size_t)G4 + u;
        gn0 = Gm[0]; gn1 = Gm[H2]; gn2 = Gm[2 * H2]; gn3 = Gm[3 * H2];
    }

    // stage h(-1) = h0 (no polling)
    if (tid < 128)
        *(float4*)(sh[0] + tid * 4) = *(const float4*)(h0 + dir * H2 + tid * 4);
    __syncthreads();

    // own slice = h elems [slice*8, slice*8+8) -> pollers tid/2 == slice skip
    bool is_poller = (tid < 128) && ((tid >> 1) != slice);

    for (int t = 0; t < TT; t++) {
        // GEMV on sh[t&1], f32x2: 32 FFMA2 per lane
        const u64* sh2 = (const u64*)(sh[t & 1]);
        u64 p0 = 0ull, p1 = 0ull, p2 = 0ull, p3 = 0ull;
#pragma unroll
        for (int q = 0; q < 8; q++) {
            u64 hv = sh2[q * 32 + lane];
            p0 = fma2(w2[0][q], hv, p0);
            p1 = fma2(w2[1][q], hv, p1);
            p2 = fma2(w2[2][q], hv, p2);
            p3 = fma2(w2[3][q], hv, p3);
        }
        float lo, hi;
        unpack2(p0, lo, hi); float a0 = lo + hi;
        unpack2(p1, lo, hi); float a1 = lo + hi;
        unpack2(p2, lo, hi); float a2 = lo + hi;
        unpack2(p3, lo, hi); float a3 = lo + hi;

        // issue G(t+2) prefetch early (2 steps of cover for DRAM latency)
        float gf0 = 0.f, gf1 = 0.f, gf2 = 0.f, gf3 = 0.f;
        if (t + 2 < TT) {
            const float* Gf = Gd + (size_t)(t + 2) * G4 + u;
            gf0 = Gf[0]; gf1 = Gf[H2]; gf2 = Gf[2 * H2]; gf3 = Gf[3 * H2];
        }

        // butterfly all-reduce (gate sums land in every lane)
#pragma unroll
        for (int off = 16; off > 0; off >>= 1) {
            a0 += __shfl_xor_sync(0xffffffffu, a0, off);
            a1 += __shfl_xor_sync(0xffffffffu, a1, off);
            a2 += __shfl_xor_sync(0xffffffffu, a2, off);
            a3 += __shfl_xor_sync(0xffffffffu, a3, off);
        }

        // redundant activation in all lanes
        float gi = a0 + gc0, gf = a1 + gc1, gg = a2 + gc2, go = a3 + gc3;
        cj = sigmoid_fast(gf) * cj + sigmoid_fast(gi) * tanh_fast(gg);
        float hj = sigmoid_fast(go) * tanh_fast(cj);

        // publish (h, tag=t) atomically to the 8 replicas (lanes 0-7)
        if (lane < NREP)
            st_rlx_pair(&d_sync[dir][lane][t & (SWIN - 1)][u * 2],
                        __float_as_uint(hj), (unsigned)t);
        // history write for k_feats (lane 8), own-unit pre-stage (lane 0)
        if (lane == 8) hout[(size_t)t * H2 + u] = hj;
        if (lane == 0) sh[(t + 1) & 1][u] = hj;

        if (t + 1 < TT) {
            // staged poll: tid<128 fetch their 4 h elems of step t
            if (is_poller) {
                const unsigned* p = &d_sync[dir][rep][t & (SWIN - 1)][tid * 8];
                unsigned tt = (unsigned)t;
                uint4 va, vb;
                do {
                    va = ld_rlx_v4u(p);
                    vb = ld_rlx_v4u(p + 4);
                } while (va.y != tt || va.w != tt || vb.y != tt || vb.w != tt);
                float4 hv;
                hv.x = __uint_as_float(va.x); hv.y = __uint_as_float(va.z);
                hv.z = __uint_as_float(vb.x); hv.w = __uint_as_float(vb.z);
                *(float4*)(sh[(t + 1) & 1] + tid * 4) = hv;
            }
            __syncthreads();
        }
        gc0 = gn0; gc1 = gn1; gc2 = gn2; gc3 = gn3;
        gn0 = gf0; gn1 = gf1; gn2 = gf2; gn3 = gf3;
    }
}

// -------------------- kernel: output projection feats = [hf|hb] @ Wout^T ----
__global__ void k_feats(const float* __restrict__ Wout,
                        const float* __restrict__ bout) {
    int t = blockIdx.x;
    int n = threadIdx.x >> 5;              // 5 warps -> 5 tags
    int lane = threadIdx.x & 31;
    const float* hf = d_h[0] + (size_t)t * H2;
    const float* hb = d_h[1] + (size_t)(TT - 1 - t) * H2;
    float s = 0.0f;
    const float* Wn = Wout + (size_t)n * (2 * H2);
#pragma unroll 4
    for (int k = lane; k < H2; k += 32) s += Wn[k] * hf[k];
#pragma unroll 4
    for (int k = lane; k < H2; k += 32) s += Wn[H2 + k] * hb[k];
#pragma unroll
    for (int off = 16; off > 0; off >>= 1) s += __shfl_xor_sync(0xffffffffu, s, off);
    if (lane == 0) d_feats[t * 8 + n] = s + bout[n];
}

// -------------------- kernel: Viterbi + backtrace (single CTA) --------------
// Lanes 0-4 hold the full forward vector in registers; backpointer computed by
// parallel equality against the fmaxf-tree max (no predicated serial chain).
__global__ void k_viterbi(const float* __restrict__ trans,
                          float* __restrict__ out, int out_size) {
    extern __shared__ float smem[];
    float* sfeat = smem;                                    // TT*8 floats
    unsigned char* sbp = (unsigned char*)(smem + TT * 8);   // TT*8 bytes

    int tid = threadIdx.x;
    const float4* d4 = (const float4*)d_feats;
    float4* s4 = (float4*)sfeat;
    for (int i = tid; i < (TT * 8) / 4; i += blockDim.x) s4[i] = d4[i];
    __syncthreads();

    if (tid < 32) {
        int lane = tid;
        float t00=trans[0], t01=trans[1], t02=trans[2], t03=trans[3], t04=trans[4];
        float t10=trans[5], t11=trans[6], t12=trans[7], t13=trans[8], t14=trans[9];
        float t20=trans[10],t21=trans[11],t22=trans[12],t23=trans[13],t24=trans[14];
        float t30=trans[15],t31=trans[16],t32=trans[17],t33=trans[18],t34=trans[19];
        float t40=trans[20],t41=trans[21],t42=trans[22],t43=trans[23],t44=trans[24];

        float f0 = (0 == START) ? 0.0f : NEGV;
        float f1 = (1 == START) ? 0.0f : NEGV;
        float f2 = (2 == START) ? 0.0f : NEGV;
        float f3 = (3 == START) ? 0.0f : NEGV;
        float f4 = (4 == START) ? 0.0f : NEGV;

        float4 ft = *(const float4*)(sfeat);
        float ft4 = sfeat[4];

        for (int t = 0; t < TT; t++) {
            float4 ftn; float ftn4 = 0.0f;
            ftn.x = ftn.y = ftn.z = ftn.w = 0.0f;
            if (t + 1 < TT) {
                ftn = *(const float4*)(sfeat + (t + 1) * 8);
                ftn4 = sfeat[(t + 1) * 8 + 4];
            }

            // candidates (parallel FADDs, reused for max and backpointer)
            float c00=f0+t00, c01=f1+t01, c02=f2+t02, c03=f3+t03, c04=f4+t04;
            float c10=f0+t10, c11=f1+t11, c12=f2+t12, c13=f3+t13, c14=f4+t14;
            float c20=f0+t20, c21=f1+t21, c22=f2+t22, c23=f3+t23, c24=f4+t24;
            float c30=f0+t30, c31=f1+t31, c32=f2+t32, c33=f3+t33, c34=f4+t34;
            float c40=f0+t40, c41=f1+t41, c42=f2+t42, c43=f3+t43, c44=f4+t44;

            float m0 = fmaxf(fmaxf(fmaxf(c00,c01), fmaxf(c02,c03)), c04);
            float m1 = fmaxf(fmaxf(fmaxf(c10,c11), fmaxf(c12,c13)), c14);
            float m2 = fmaxf(fmaxf(fmaxf(c20,c21), fmaxf(c22,c23)), c24);
            float m3 = fmaxf(fmaxf(fmaxf(c30,c31), fmaxf(c32,c33)), c34);
            float m4 = fmaxf(fmaxf(fmaxf(c40,c41), fmaxf(c42,c43)), c44);

            // backpointers: first candidate equal to the max (bit-exact);
            // lanes 0-4 each store one tag's bp (parallel equality, SEL cascade)
            if (lane < NTAGS) {
                float mn, d0, d1, d2, d3, d4;
                switch (lane) {
                    case 0: mn=m0; d0=c00; d1=c01; d2=c02; d3=c03; d4=c04; break;
                    case 1: mn=m1; d0=c10; d1=c11; d2=c12; d3=c13; d4=c14; break;
                    case 2: mn=m2; d0=c20; d1=c21; d2=c22; d3=c23; d4=c24; break;
                    case 3: mn=m3; d0=c30; d1=c31; d2=c32; d3=c33; d4=c34; break;
                    default: mn=m4; d0=c40; d1=c41; d2=c42; d3=c43; d4=c44; break;
                }
                int bp = (d0 == mn) ? 0 : (d1 == mn) ? 1 : (d2 == mn) ? 2
                        : (d3 == mn) ? 3 : 4;
                sbp[t * 8 + lane] = (unsigned char)bp;
            }

            f0 = m0 + ft.x; f1 = m1 + ft.y; f2 = m2 + ft.z; f3 = m3 + ft.w; f4 = m4 + ft4;
            ft = ftn; ft4 = ftn4;
        }

        if (lane == 0) {
            float fv[NTAGS] = {f0, f1, f2, f3, f4};
            float best = fv[0] + trans[STOP * NTAGS + 0];
            int bt = 0;
#pragma unroll
            for (int p = 1; p < NTAGS; p++) {
                float s = fv[p] + trans[STOP * NTAGS + p];
                if (s > best) { best = s; bt = p; }
            }
            if (out_size > 0) out[0] = best;
            int tag = bt;
            if (1 + (TT - 1) < out_size) out[1 + (TT - 1)] = (float)tag;
            for (int t = TT - 1; t >= 1; t--) {
                tag = sbp[t * 8 + tag];
                if (t < out_size) out[t] = (float)tag;
            }
        }
    }
}

// -------------------- launcher ----------------------------------------------
extern "C" void kernel_launch(void* const* d_in, const int* in_sizes, int n_in,
                              void* d_out, int out_size) {
    const int*   sent  = (const int*)d_in[0];
    const float* h0    = (const float*)d_in[1];
    const float* c0    = (const float*)d_in[2];
    const float* embed = (const float*)d_in[3];
    const float* Wih_f = (const float*)d_in[4];
    const float* Whh_f = (const float*)d_in[5];
    const float* bih_f = (const float*)d_in[6];
    const float* bhh_f = (const float*)d_in[7];
    const float* Wih_b = (const float*)d_in[8];
    const float* Whh_b = (const float*)d_in[9];
    const float* bih_b = (const float*)d_in[10];
    const float* bhh_b = (const float*)d_in[11];
    const float* Wout  = (const float*)d_in[12];
    const float* bout  = (const float*)d_in[13];
    const float* trans = (const float*)d_in[14];
    float* out = (float*)d_out;

    k_init<<<64, 512>>>();
    dim3 gg(G4 / 128, TT / 128, 2);
    k_gemm<<<gg, 256>>>(sent, embed, Wih_f, Wih_b,
                        bih_f, bhh_f, bih_b, bhh_b);
    k_recur<<<2 * NCTA, 256>>>(Whh_f, Whh_b, h0, c0);
    k_feats<<<TT, 160>>>(Wout, bout);

    int vit_smem = TT * 8 * (int)sizeof(float) + TT * 8;   // 163840 B
    cudaFuncSetAttribute(k_viterbi, cudaFuncAttributeMaxDynamicSharedMemorySize,
                         vit_smem);
    k_viterbi<<<1, 128, vit_smem>>>(trans, out, out_size);
}

// round 16
// speedup vs baseline: 1.2938x; 1.1547x over previous
#include <cuda_runtime.h>

// Problem constants
#define TT    4096
#define EMB   1024
#define H2    512
#define G4    2048       // 4 * H2
#define NTAGS 5
#define START 3
#define STOP  4
#define NEGV  -10000.0f

// Recurrence: 64 CTAs per direction, 8 hidden units each (R12 structure)
#define NCTA   64
#define HPER   8
#define NREP   8         // sync replication factor (poll-traffic spreading)
#define SWIN   8         // sync ring depth (slot = t & 7)

typedef unsigned long long u64;

// -------------------- scratch (static device globals; no allocs) ------------
__device__ float d_G[2][TT * G4];               // input preactivations (64 MB)
__device__ float d_h[2][TT * H2];               // hidden history for feats (16 MB)
__device__ unsigned d_sync[2][NREP][SWIN][H2 * 2];  // (h,tag) pairs — 512 KB, L2-hot
__device__ float d_feats[TT * 8];               // tag scores, stride 8

// -------------------- helpers ----------------------------------------------
__device__ __forceinline__ uint4 ld_rlx_v4u(const unsigned* p) {
    uint4 v;
    asm volatile("ld.relaxed.gpu.global.v4.u32 {%0,%1,%2,%3}, [%4];"
                 : "=r"(v.x), "=r"(v.y), "=r"(v.z), "=r"(v.w) : "l"(p) : "memory");
    return v;
}
__device__ __forceinline__ void st_rlx_pair(unsigned* p, unsigned hbits, unsigned tag) {
    unsigned long long v = ((unsigned long long)tag << 32) | (unsigned long long)hbits;
    asm volatile("st.relaxed.gpu.global.b64 [%0], %1;" :: "l"(p), "l"(v) : "memory");
}
__device__ __forceinline__ float tanh_fast(float x) {
    float y;
    asm("tanh.approx.f32 %0, %1;" : "=f"(y) : "f"(x));
    return y;
}
__device__ __forceinline__ float sigmoid_fast(float x) {
    return fmaf(0.5f, tanh_fast(0.5f * x), 0.5f);
}
__device__ __forceinline__ u64 fma2(u64 a, u64 b, u64 c) {
    u64 d;
    asm("fma.rn.f32x2 %0, %1, %2, %3;" : "=l"(d) : "l"(a), "l"(b), "l"(c));
    return d;
}
__device__ __forceinline__ u64 pack2(float lo, float hi) {
    u64 d;
    asm("mov.b64 %0, {%1, %2};" : "=l"(d) : "f"(lo), "f"(hi));
    return d;
}
__device__ __forceinline__ void unpack2(u64 v, float& lo, float& hi) {
    asm("mov.b64 {%0, %1}, %2;" : "=f"(lo), "=f"(hi) : "l"(v));
}

// -------------------- kernel: init sync ring tags ----------------------------
// d_sync = 2*8*8*1024 uints = 131072 uints = 32768 uint4
__global__ void k_init() {
    int i = blockIdx.x * blockDim.x + threadIdx.x;
    uint4 s; s.x = 0xFFFFFFFFu; s.y = 0xFFFFFFFFu; s.z = 0xFFFFFFFFu; s.w = 0xFFFFFFFFu;
    if (i < 32768) ((uint4*)d_sync)[i] = s;
}

// -------------------- kernel: input GEMM  G = embed[sent] @ Wih^T + bias ----
// C tile 128x128, K tile 16, 256 threads, 8 rows x 4 col-pairs per thread,
// f32x2 FMA (32 FFMA2/k instead of 64 FFMA), double-buffered smem, embedding
// gather fused into the A load. dir==1 reads tokens in reverse.
__global__ __launch_bounds__(256) void k_gemm(
    const int*   __restrict__ sent, const float* __restrict__ embed,
    const float* __restrict__ Wf, const float* __restrict__ Wb,
    const float* __restrict__ bihf, const float* __restrict__ bhhf,
    const float* __restrict__ bihb, const float* __restrict__ bhhb) {
    int dir = blockIdx.z;
    const float* W  = dir ? Wb   : Wf;
    const float* b1 = dir ? bihb : bihf;
    const float* b2 = dir ? bhhb : bhhf;
    float* Gp = d_G[dir];

    __shared__ __align__(16) float As[2][16 * 128];
    __shared__ __align__(16) float Bs[2][16 * 128];

    int tid = threadIdx.x;
    int m0 = blockIdx.y * 128;
    int n0 = blockIdx.x * 128;
    int ty = tid >> 4, tx = tid & 15;

    int lrow[2], lkq[2];
    const float* Arow[2];
    const float* Brow[2];
#pragma unroll
    for (int h = 0; h < 2; h++) {
        int f = tid + h * 256;
        lrow[h] = f >> 2; lkq[h] = f & 3;
        int srcRow = m0 + lrow[h];
        if (dir) srcRow = TT - 1 - srcRow;
        int token = sent[srcRow];
        Arow[h] = embed + (size_t)token * EMB;
        Brow[h] = W + (size_t)(n0 + lrow[h]) * EMB;
    }

    u64 acc[8][4];
#pragma unroll
    for (int i = 0; i < 8; i++)
#pragma unroll
        for (int j = 0; j < 4; j++) acc[i][j] = 0ull;

#pragma unroll
    for (int h = 0; h < 2; h++) {
        float4 va = *(const float4*)(Arow[h] + lkq[h] * 4);
        float4 vb = *(const float4*)(Brow[h] + lkq[h] * 4);
        As[0][(lkq[h]*4+0)*128 + lrow[h]] = va.x;
        As[0][(lkq[h]*4+1)*128 + lrow[h]] = va.y;
        As[0][(lkq[h]*4+2)*128 + lrow[h]] = va.z;
        As[0][(lkq[h]*4+3)*128 + lrow[h]] = va.w;
        Bs[0][(lkq[h]*4+0)*128 + lrow[h]] = vb.x;
        Bs[0][(lkq[h]*4+1)*128 + lrow[h]] = vb.y;
        Bs[0][(lkq[h]*4+2)*128 + lrow[h]] = vb.z;
        Bs[0][(lkq[h]*4+3)*128 + lrow[h]] = vb.w;
    }
    __syncthreads();

    for (int kt = 0; kt < EMB / 16; kt++) {
        int p = kt & 1;
        float4 va[2], vb[2];
        if (kt < EMB / 16 - 1) {
            int k0 = (kt + 1) * 16;
#pragma unroll
            for (int h = 0; h < 2; h++) {
                va[h] = *(const float4*)(Arow[h] + k0 + lkq[h] * 4);
                vb[h] = *(const float4*)(Brow[h] + k0 + lkq[h] * 4);
            }
        }
        const u64* B2 = (const u64*)(Bs[p]);
#pragma unroll
        for (int k = 0; k < 16; k++) {
            u64 a2[8];
#pragma unroll
            for (int i = 0; i < 8; i++) {
                float av = As[p][k * 128 + ty * 8 + i];
                a2[i] = pack2(av, av);
            }
            u64 bb[4];
#pragma unroll
            for (int j = 0; j < 4; j++) bb[j] = B2[k * 64 + tx + j * 16];
#pragma unroll
            for (int i = 0; i < 8; i++)
#pragma unroll
                for (int j = 0; j < 4; j++) acc[i][j] = fma2(a2[i], bb[j], acc[i][j]);
        }
        if (kt < EMB / 16 - 1) {
            int q = 1 - p;
            __syncthreads();
#pragma unroll
            for (int h = 0; h < 2; h++) {
                As[q][(lkq[h]*4+0)*128 + lrow[h]] = va[h].x;
                As[q][(lkq[h]*4+1)*128 + lrow[h]] = va[h].y;
                As[q][(lkq[h]*4+2)*128 + lrow[h]] = va[h].z;
                As[q][(lkq[h]*4+3)*128 + lrow[h]] = va[h].w;
                Bs[q][(lkq[h]*4+0)*128 + lrow[h]] = vb[h].x;
                Bs[q][(lkq[h]*4+1)*128 + lrow[h]] = vb[h].y;
                Bs[q][(lkq[h]*4+2)*128 + lrow[h]] = vb[h].z;
                Bs[q][(lkq[h]*4+3)*128 + lrow[h]] = vb[h].w;
            }
            __syncthreads();
        }
    }

    // epilogue: cols n0 + tx*2 + j*32 (pairs)
#pragma unroll
    for (int j = 0; j < 4; j++) {
        int n = n0 + tx * 2 + j * 32;
        float bx = b1[n]     + b2[n];
        float by = b1[n + 1] + b2[n + 1];
#pragma unroll
        for (int i = 0; i < 8; i++) {
            int m = m0 + ty * 8 + i;
            float lo, hi;
            unpack2(acc[i][j], lo, hi);
            float2 o; o.x = lo + bx; o.y = hi + by;
            *(float2*)(Gp + (size_t)m * G4 + n) = o;
        }
    }
}

// -------------------- kernel: persistent LSTM recurrence --------------------
// 128 CTAs (64/dir), 256 threads = 8 warps; warp w owns hidden unit hbase+w.
// R12 verbatim: staged poll (tid<128, two v4 loads) + ONE __syncthreads/step;
// sync via 512KB L2-resident (h,tag) ring; GEMV in f32x2.
__global__ void __launch_bounds__(256, 1) k_recur(
    const float* __restrict__ Whh_f, const float* __restrict__ Whh_b,
    const float* __restrict__ h0, const float* __restrict__ c0) {
    int dir   = blockIdx.x >> 6;
    int slice = blockIdx.x & 63;
    int hbase = slice * HPER;
    const float* Whh = dir ? Whh_b : Whh_f;
    const float* Gd  = d_G[dir];
    float* hout = d_h[dir];

    int tid = threadIdx.x;
    int w = tid >> 5;            // warp -> hidden unit u = hbase + w
    int lane = tid & 31;
    int u = hbase + w;
    int rep = slice & 7;         // which replica this CTA polls

    // weights as f32x2 pairs: pair q of gate g = Whh[row*H2 + q*64 + lane*2 ..+1]
    u64 w2[4][8];
#pragma unroll
    for (int g = 0; g < 4; g++) {
        const u64* Wr = (const u64*)(Whh + (size_t)(g * H2 + u) * H2);
#pragma unroll
        for (int q = 0; q < 8; q++) w2[g][q] = Wr[q * 32 + lane];
    }

    __shared__ __align__(16) float sh[2][H2];

    float cj = c0[dir * H2 + u];             // identical in all lanes

    // G prefetch pipeline, depth 2 (G is a DRAM stream)
    float gc0, gc1, gc2, gc3;                // step t
    float gn0, gn1, gn2, gn3;                // step t+1
    {
        const float* Gt = Gd + u;
        gc0 = Gt[0]; gc1 = Gt[H2]; gc2 = Gt[2 * H2]; gc3 = Gt[3 * H2];
        const float* Gm = Gd + (size_t)G4 + u;
        gn0 = Gm[0]; gn1 = Gm[H2]; gn2 = Gm[2 * H2]; gn3 = Gm[3 * H2];
    }

    // stage h(-1) = h0 (no polling)
    if (tid < 128)
        *(float4*)(sh[0] + tid * 4) = *(const float4*)(h0 + dir * H2 + tid * 4);
    __syncthreads();

    // own slice = h elems [slice*8, slice*8+8) -> pollers tid/2 == slice skip
    bool is_poller = (tid < 128) && ((tid >> 1) != slice);

    for (int t = 0; t < TT; t++) {
        // GEMV on sh[t&1], f32x2: 32 FFMA2 per lane
        const u64* sh2 = (const u64*)(sh[t & 1]);
        u64 p0 = 0ull, p1 = 0ull, p2 = 0ull, p3 = 0ull;
#pragma unroll
        for (int q = 0; q < 8; q++) {
            u64 hv = sh2[q * 32 + lane];
            p0 = fma2(w2[0][q], hv, p0);
            p1 = fma2(w2[1][q], hv, p1);
            p2 = fma2(w2[2][q], hv, p2);
            p3 = fma2(w2[3][q], hv, p3);
        }
        float lo, hi;
        unpack2(p0, lo, hi); float a0 = lo + hi;
        unpack2(p1, lo, hi); float a1 = lo + hi;
        unpack2(p2, lo, hi); float a2 = lo + hi;
        unpack2(p3, lo, hi); float a3 = lo + hi;

        // issue G(t+2) prefetch early (2 steps of cover for DRAM latency)
        float gf0 = 0.f, gf1 = 0.f, gf2 = 0.f, gf3 = 0.f;
        if (t + 2 < TT) {
            const float* Gf = Gd + (size_t)(t + 2) * G4 + u;
            gf0 = Gf[0]; gf1 = Gf[H2]; gf2 = Gf[2 * H2]; gf3 = Gf[3 * H2];
        }

        // butterfly all-reduce (gate sums land in every lane)
#pragma unroll
        for (int off = 16; off > 0; off >>= 1) {
            a0 += __shfl_xor_sync(0xffffffffu, a0, off);
            a1 += __shfl_xor_sync(0xffffffffu, a1, off);
            a2 += __shfl_xor_sync(0xffffffffu, a2, off);
            a3 += __shfl_xor_sync(0xffffffffu, a3, off);
        }

        // redundant activation in all lanes
        float gi = a0 + gc0, gf = a1 + gc1, gg = a2 + gc2, go = a3 + gc3;
        cj = sigmoid_fast(gf) * cj + sigmoid_fast(gi) * tanh_fast(gg);
        float hj = sigmoid_fast(go) * tanh_fast(cj);

        // publish (h, tag=t) atomically to the 8 replicas (lanes 0-7)
        if (lane < NREP)
            st_rlx_pair(&d_sync[dir][lane][t & (SWIN - 1)][u * 2],
                        __float_as_uint(hj), (unsigned)t);
        // history write for k_feats (lane 8), own-unit pre-stage (lane 0)
        if (lane == 8) hout[(size_t)t * H2 + u] = hj;
        if (lane == 0) sh[(t + 1) & 1][u] = hj;

        if (t + 1 < TT) {
            // staged poll: tid<128 fetch their 4 h elems of step t
            if (is_poller) {
                const unsigned* p = &d_sync[dir][rep][t & (SWIN - 1)][tid * 8];
                unsigned tt = (unsigned)t;
                uint4 va, vb;
                do {
                    va = ld_rlx_v4u(p);
                    vb = ld_rlx_v4u(p + 4);
                } while (va.y != tt || va.w != tt || vb.y != tt || vb.w != tt);
                float4 hv;
                hv.x = __uint_as_float(va.x); hv.y = __uint_as_float(va.z);
                hv.z = __uint_as_float(vb.x); hv.w = __uint_as_float(vb.z);
                *(float4*)(sh[(t + 1) & 1] + tid * 4) = hv;
            }
            __syncthreads();
        }
        gc0 = gn0; gc1 = gn1; gc2 = gn2; gc3 = gn3;
        gn0 = gf0; gn1 = gf1; gn2 = gf2; gn3 = gf3;
    }
}

// -------------------- kernel: output projection feats = [hf|hb] @ Wout^T ----
__global__ void k_feats(const float* __restrict__ Wout,
                        const float* __restrict__ bout) {
    int t = blockIdx.x;
    int n = threadIdx.x >> 5;              // 5 warps -> 5 tags
    int lane = threadIdx.x & 31;
    const float* hf = d_h[0] + (size_t)t * H2;
    const float* hb = d_h[1] + (size_t)(TT - 1 - t) * H2;
    float s = 0.0f;
    const float* Wn = Wout + (size_t)n * (2 * H2);
#pragma unroll 4
    for (int k = lane; k < H2; k += 32) s += Wn[k] * hf[k];
#pragma unroll 4
    for (int k = lane; k < H2; k += 32) s += Wn[H2 + k] * hb[k];
#pragma unroll
    for (int off = 16; off > 0; off >>= 1) s += __shfl_xor_sync(0xffffffffu, s, off);
    if (lane == 0) d_feats[t * 8 + n] = s + bout[n];
}

// -------------------- kernel: Viterbi + backtrace (single CTA) --------------
// Lanes 0-4 hold the full forward vector in registers, redundantly compute
// all 5 updates; feat loads software-pipelined one step ahead. (R12 version.)
__global__ void k_viterbi(const float* __restrict__ trans,
                          float* __restrict__ out, int out_size) {
    extern __shared__ float smem[];
    float* sfeat = smem;                                    // TT*8 floats
    unsigned char* sbp = (unsigned char*)(smem + TT * 8);   // TT*8 bytes

    int tid = threadIdx.x;
    const float4* d4 = (const float4*)d_feats;
    float4* s4 = (float4*)sfeat;
    for (int i = tid; i < (TT * 8) / 4; i += blockDim.x) s4[i] = d4[i];
    __syncthreads();

    if (tid < 32) {
        int lane = tid;
        int n = lane < NTAGS ? lane : NTAGS - 1;
        float t00=trans[0], t01=trans[1], t02=trans[2], t03=trans[3], t04=trans[4];
        float t10=trans[5], t11=trans[6], t12=trans[7], t13=trans[8], t14=trans[9];
        float t20=trans[10],t21=trans[11],t22=trans[12],t23=trans[13],t24=trans[14];
        float t30=trans[15],t31=trans[16],t32=trans[17],t33=trans[18],t34=trans[19];
        float t40=trans[20],t41=trans[21],t42=trans[22],t43=trans[23],t44=trans[24];
        float trn0 = trans[n*5+0], trn1 = trans[n*5+1], trn2 = trans[n*5+2],
              trn3 = trans[n*5+3], trn4 = trans[n*5+4];

        float f0 = (0 == START) ? 0.0f : NEGV;
        float f1 = (1 == START) ? 0.0f : NEGV;
        float f2 = (2 == START) ? 0.0f : NEGV;
        float f3 = (3 == START) ? 0.0f : NEGV;
        float f4 = (4 == START) ? 0.0f : NEGV;

        float4 ft = *(const float4*)(sfeat);
        float ft4 = sfeat[4];

        for (int t = 0; t < TT; t++) {
            float4 ftn; float ftn4 = 0.0f;
            ftn.x = ftn.y = ftn.z = ftn.w = 0.0f;
            if (t + 1 < TT) {
                ftn = *(const float4*)(sfeat + (t + 1) * 8);
                ftn4 = sfeat[(t + 1) * 8 + 4];
            }

            float b = f0 + trn0; int bp = 0; float v;
            v = f1 + trn1; if (v > b) { b = v; bp = 1; }
            v = f2 + trn2; if (v > b) { b = v; bp = 2; }
            v = f3 + trn3; if (v > b) { b = v; bp = 3; }
            v = f4 + trn4; if (v > b) { b = v; bp = 4; }
            if (lane < NTAGS) sbp[t * 8 + lane] = (unsigned char)bp;

            float m0 = fmaxf(fmaxf(fmaxf(f0+t00, f1+t01), fmaxf(f2+t02, f3+t03)), f4+t04);
            float m1 = fmaxf(fmaxf(fmaxf(f0+t10, f1+t11), fmaxf(f2+t12, f3+t13)), f4+t14);
            float m2 = fmaxf(fmaxf(fmaxf(f0+t20, f1+t21), fmaxf(f2+t22, f3+t23)), f4+t24);
            float m3 = fmaxf(fmaxf(fmaxf(f0+t30, f1+t31), fmaxf(f2+t32, f3+t33)), f4+t34);
            float m4 = fmaxf(fmaxf(fmaxf(f0+t40, f1+t41), fmaxf(f2+t42, f3+t43)), f4+t44);
            f0 = m0 + ft.x; f1 = m1 + ft.y; f2 = m2 + ft.z; f3 = m3 + ft.w; f4 = m4 + ft4;

            ft = ftn; ft4 = ftn4;
        }

        if (lane == 0) {
            float fv[NTAGS] = {f0, f1, f2, f3, f4};
            float best = fv[0] + trans[STOP * NTAGS + 0];
            int bt = 0;
#pragma unroll
            for (int p = 1; p < NTAGS; p++) {
                float s = fv[p] + trans[STOP * NTAGS + p];
                if (s > best) { best = s; bt = p; }
            }
            if (out_size > 0) out[0] = best;
            int tag = bt;
            if (1 + (TT - 1) < out_size) out[1 + (TT - 1)] = (float)tag;
            for (int t = TT - 1; t >= 1; t--) {
                tag = sbp[t * 8 + tag];
                if (t < out_size) out[t] = (float)tag;
            }
        }
    }
}

// -------------------- launcher ----------------------------------------------
extern "C" void kernel_launch(void* const* d_in, const int* in_sizes, int n_in,
                              void* d_out, int out_size) {
    const int*   sent  = (const int*)d_in[0];
    const float* h0    = (const float*)d_in[1];
    const float* c0    = (const float*)d_in[2];
    const float* embed = (const float*)d_in[3];
    const float* Wih_f = (const float*)d_in[4];
    const float* Whh_f = (const float*)d_in[5];
    const float* bih_f = (const float*)d_in[6];
    const float* bhh_f = (const float*)d_in[7];
    const float* Wih_b = (const float*)d_in[8];
    const float* Whh_b = (const float*)d_in[9];
    const float* bih_b = (const float*)d_in[10];
    const float* bhh_b = (const float*)d_in[11];
    const float* Wout  = (const float*)d_in[12];
    const float* bout  = (const float*)d_in[13];
    const float* trans = (const float*)d_in[14];
    float* out = (float*)d_out;

    k_init<<<64, 512>>>();
    dim3 gg(G4 / 128, TT / 128, 2);
    k_gemm<<<gg, 256>>>(sent, embed, Wih_f, Wih_b,
                        bih_f, bhh_f, bih_b, bhh_b);
    k_recur<<<2 * NCTA, 256>>>(Whh_f, Whh_b, h0, c0);
    k_feats<<<TT, 160>>>(Wout, bout);

    int vit_smem = TT * 8 * (int)sizeof(float) + TT * 8;   // 163840 B
    cudaFuncSetAttribute(k_viterbi, cudaFuncAttributeMaxDynamicSharedMemorySize,
                         vit_smem);
    k_viterbi<<<1, 128, vit_smem>>>(trans, out, out_size);
}